// round 5
// baseline (speedup 1.0000x reference)
#include <cuda_runtime.h>

// LSTM B=8192, T=512, I=12, H=20 (i,f,g,o), zero init; Linear(H->10) on h_T.
//
// k-vectorized f32x2 with ALL weights held in registers (64 u64/thread):
// inner loop reads only activations from SMEM (16 LDS.128/thread-step vs 48).
//  - Block: 160 threads (5 warps), BPB=16, grid=512, 2 blocks/SM resident.
//  - Warp wg: lane = usub*8+g -> unit u = 4*wg+usub, batches g and g+8.
//  - Thread/step: 128 fma2, 16 activation LDS.128, scalar epilogue with bias.
//  - x prefetched to regs one 4-step chunk ahead; double-buffered SMEM.

#define LSTM_H   20
#define LSTM_I   12
#define LSTM_T   512
#define BPB      16
#define THREADS  160
#define GRID     512
#define XROW     52

typedef unsigned long long u64;

__device__ __forceinline__ void unpack2(u64 v, float& lo, float& hi) {
    asm("mov.b64 {%0, %1}, %2;" : "=f"(lo), "=f"(hi) : "l"(v));
}
__device__ __forceinline__ u64 fma2(u64 a, u64 b, u64 c) {
    u64 r; asm("fma.rn.f32x2 %0, %1, %2, %3;" : "=l"(r) : "l"(a), "l"(b), "l"(c));
    return r;
}
__device__ __forceinline__ float tanhA(float x) {
    float y; asm("tanh.approx.f32 %0, %1;" : "=f"(y) : "f"(x)); return y;
}
__device__ __forceinline__ float sigA(float x) {
    return fmaf(tanhA(0.5f * x), 0.5f, 0.5f);
}

__global__ void __launch_bounds__(THREADS, 2)
lstm_kernel(const float* __restrict__ x,
            const float* __restrict__ w_ih,
            const float* __restrict__ w_hh,
            const float* __restrict__ b_ih,
            const float* __restrict__ b_hh,
            const float* __restrict__ w_out,
            const float* __restrict__ b_out,
            float* __restrict__ out)
{
    __shared__ __align__(16) float wih_s[80 * LSTM_I];        // 3840 B
    __shared__ __align__(16) float whh_s[80 * LSTM_H];        // 6400 B
    __shared__ __align__(16) float hbuf[2][BPB * LSTM_H];     // 2560 B
    __shared__ __align__(16) float xs[2][BPB * XROW];         // 6656 B

    const int tid  = threadIdx.x;
    const int lane = tid & 31;
    const int wg   = tid >> 5;          // 0..4
    const int usub = lane >> 3;         // 0..3
    const int g    = lane & 7;          // batch group
    const int u    = 4 * wg + usub;     // unit 0..19
    const int bA   = g, bB = g + 8;
    const int b0   = blockIdx.x * BPB;

    // ---- stage weights to SMEM (one-time) ----
    for (int i = tid; i < 80 * LSTM_I; i += THREADS) wih_s[i] = w_ih[i];
    for (int i = tid; i < 80 * LSTM_H; i += THREADS) whh_s[i] = w_hh[i];
    for (int i = tid; i < BPB * LSTM_H; i += THREADS) hbuf[0][i] = 0.f;

    // scalar biases (added in epilogue)
    const float bI = b_ih[0 * LSTM_H + u] + b_hh[0 * LSTM_H + u];
    const float bF = b_ih[1 * LSTM_H + u] + b_hh[1 * LSTM_H + u];
    const float bG = b_ih[2 * LSTM_H + u] + b_hh[2 * LSTM_H + u];
    const float bO = b_ih[3 * LSTM_H + u] + b_hh[3 * LSTM_H + u];

    __syncthreads();

    // ---- copy this thread's 4 gate rows into registers ----
    u64 wxI[6], wxF[6], wxG[6], wxO[6];     // x-part (12 floats each)
    u64 whI[10], whF[10], whG[10], whO[10]; // h-part (20 floats each)
    {
        const u64* wi0 = (const u64*)&wih_s[(0 * LSTM_H + u) * LSTM_I];
        const u64* wi1 = (const u64*)&wih_s[(1 * LSTM_H + u) * LSTM_I];
        const u64* wi2 = (const u64*)&wih_s[(2 * LSTM_H + u) * LSTM_I];
        const u64* wi3 = (const u64*)&wih_s[(3 * LSTM_H + u) * LSTM_I];
        #pragma unroll
        for (int k = 0; k < 6; k++) {
            wxI[k] = wi0[k]; wxF[k] = wi1[k]; wxG[k] = wi2[k]; wxO[k] = wi3[k];
        }
        const u64* wh0 = (const u64*)&whh_s[(0 * LSTM_H + u) * LSTM_H];
        const u64* wh1 = (const u64*)&whh_s[(1 * LSTM_H + u) * LSTM_H];
        const u64* wh2 = (const u64*)&whh_s[(2 * LSTM_H + u) * LSTM_H];
        const u64* wh3 = (const u64*)&whh_s[(3 * LSTM_H + u) * LSTM_H];
        #pragma unroll
        for (int k = 0; k < 10; k++) {
            whI[k] = wh0[k]; whF[k] = wh1[k]; whG[k] = wh2[k]; whO[k] = wh3[k];
        }
    }

    // ---- x prefetch: 192 float4 items per 4-step chunk, 160 threads ----
    const float4* x4 = (const float4*)x;
    const int i0 = tid, i1 = tid + THREADS;
    const int pb0 = i0 / 12, pq0 = i0 - pb0 * 12;
    const int pb1 = i1 / 12, pq1 = i1 - pb1 * 12;
    const bool has1 = (i1 < BPB * 12);
    const long gbase0 = (long)(b0 + pb0) * 1536 + pq0;
    const long gbase1 = (long)(b0 + pb1) * 1536 + pq1;
    float4 pf0, pf1;

    {
        float4 v = x4[gbase0];
        *(float4*)&xs[0][pb0 * XROW + 4 * pq0] = v;
        if (has1) {
            float4 v1 = x4[gbase1];
            *(float4*)&xs[0][pb1 * XROW + 4 * pq1] = v1;
        }
        pf0 = x4[gbase0 + 12];
        if (has1) pf1 = x4[gbase1 + 12];
    }
    __syncthreads();

    float cA = 0.f, cB = 0.f;

    #pragma unroll 1
    for (int t = 0; t < LSTM_T; t++) {
        const int tt = t & 3;
        if (tt == 0 && t > 0) {
            const int buf = (t >> 2) & 1;
            *(float4*)&xs[buf][pb0 * XROW + 4 * pq0] = pf0;
            if (has1) *(float4*)&xs[buf][pb1 * XROW + 4 * pq1] = pf1;
            if (t + 4 < LSTM_T) {
                pf0 = x4[gbase0 + (long)(t + 4) * 3];
                if (has1) pf1 = x4[gbase1 + (long)(t + 4) * 3];
            }
            __syncthreads();
        }

        const int cur = t & 1, nxt = cur ^ 1;

        u64 aA0 = 0, aA1 = 0, aA2 = 0, aA3 = 0;
        u64 aB0 = 0, aB1 = 0, aB2 = 0, aB3 = 0;

        // ---- x part: 6 u64 per batch ----
        {
            const u64* xrA = (const u64*)&xs[(t >> 2) & 1][bA * XROW + tt * LSTM_I];
            const u64* xrB = (const u64*)&xs[(t >> 2) & 1][bB * XROW + tt * LSTM_I];
            #pragma unroll
            for (int k = 0; k < 6; k += 2) {
                ulonglong2 xA = *(const ulonglong2*)(xrA + k);
                ulonglong2 xB = *(const ulonglong2*)(xrB + k);
                aA0 = fma2(wxI[k], xA.x, aA0); aA0 = fma2(wxI[k+1], xA.y, aA0);
                aA1 = fma2(wxF[k], xA.x, aA1); aA1 = fma2(wxF[k+1], xA.y, aA1);
                aA2 = fma2(wxG[k], xA.x, aA2); aA2 = fma2(wxG[k+1], xA.y, aA2);
                aA3 = fma2(wxO[k], xA.x, aA3); aA3 = fma2(wxO[k+1], xA.y, aA3);
                aB0 = fma2(wxI[k], xB.x, aB0); aB0 = fma2(wxI[k+1], xB.y, aB0);
                aB1 = fma2(wxF[k], xB.x, aB1); aB1 = fma2(wxF[k+1], xB.y, aB1);
                aB2 = fma2(wxG[k], xB.x, aB2); aB2 = fma2(wxG[k+1], xB.y, aB2);
                aB3 = fma2(wxO[k], xB.x, aB3); aB3 = fma2(wxO[k+1], xB.y, aB3);
            }
        }

        // ---- h part: 10 u64 per batch ----
        {
            const u64* hrA = (const u64*)&hbuf[cur][bA * LSTM_H];
            const u64* hrB = (const u64*)&hbuf[cur][bB * LSTM_H];
            #pragma unroll
            for (int k = 0; k < 10; k += 2) {
                ulonglong2 hA = *(const ulonglong2*)(hrA + k);
                ulonglong2 hB = *(const ulonglong2*)(hrB + k);
                aA0 = fma2(whI[k], hA.x, aA0); aA0 = fma2(whI[k+1], hA.y, aA0);
                aA1 = fma2(whF[k], hA.x, aA1); aA1 = fma2(whF[k+1], hA.y, aA1);
                aA2 = fma2(whG[k], hA.x, aA2); aA2 = fma2(whG[k+1], hA.y, aA2);
                aA3 = fma2(whO[k], hA.x, aA3); aA3 = fma2(whO[k+1], hA.y, aA3);
                aB0 = fma2(whI[k], hB.x, aB0); aB0 = fma2(whI[k+1], hB.y, aB0);
                aB1 = fma2(whF[k], hB.x, aB1); aB1 = fma2(whF[k+1], hB.y, aB1);
                aB2 = fma2(whG[k], hB.x, aB2); aB2 = fma2(whG[k+1], hB.y, aB2);
                aB3 = fma2(whO[k], hB.x, aB3); aB3 = fma2(whO[k+1], hB.y, aB3);
            }
        }

        // ---- horizontal add + bias + cell update ----
        {
            float lo, hi;
            unpack2(aA0, lo, hi); float gi = lo + hi + bI;
            unpack2(aA1, lo, hi); float gf = lo + hi + bF;
            unpack2(aA2, lo, hi); float gg = lo + hi + bG;
            unpack2(aA3, lo, hi); float go = lo + hi + bO;
            cA = sigA(gf) * cA + sigA(gi) * tanhA(gg);
            hbuf[nxt][bA * LSTM_H + u] = sigA(go) * tanhA(cA);
        }
        {
            float lo, hi;
            unpack2(aB0, lo, hi); float gi = lo + hi + bI;
            unpack2(aB1, lo, hi); float gf = lo + hi + bF;
            unpack2(aB2, lo, hi); float gg = lo + hi + bG;
            unpack2(aB3, lo, hi); float go = lo + hi + bO;
            cB = sigA(gf) * cB + sigA(gi) * tanhA(gg);
            hbuf[nxt][bB * LSTM_H + u] = sigA(go) * tanhA(cB);
        }
        __syncthreads();
    }

    // ---- output Linear (final h in hbuf[0]: t=511 -> nxt=0) ----
    {
        const int bl = tid / 10, k = tid - bl * 10;   // 16 x 10 = 160
        float sum = b_out[k];
        #pragma unroll
        for (int j = 0; j < LSTM_H; j++)
            sum = fmaf(hbuf[0][bl * LSTM_H + j], w_out[k * LSTM_H + j], sum);
        out[(long)(b0 + bl) * 10 + k] = sum;
    }
}

extern "C" void kernel_launch(void* const* d_in, const int* in_sizes, int n_in,
                              void* d_out, int out_size)
{
    const float* x     = (const float*)d_in[0];
    const float* w_ih  = (const float*)d_in[1];
    const float* w_hh  = (const float*)d_in[2];
    const float* b_ih  = (const float*)d_in[3];
    const float* b_hh  = (const float*)d_in[4];
    const float* w_out = (const float*)d_in[5];
    const float* b_out = (const float*)d_in[6];
    float* out = (float*)d_out;

    lstm_kernel<<<GRID, THREADS>>>(x, w_ih, w_hh, b_ih, b_hh, w_out, b_out, out);
}